// round 13
// baseline (speedup 1.0000x reference)
#include <cuda_runtime.h>
#include <cuda_bf16.h>
#include <math_constants.h>

#define BATCH 64
#define SEQ   256
#define TCH   16
#define VOC   262
#define EMB   64
#define HID   32
#define G3    96
#define NSEQ  (BATCH*SEQ)

// Tables (device globals — no allocation allowed)
// Permuted GI rows: pos(gate,j) = gate*32 + tig*8 + hg*2 + e
// r,z entries pre-scaled by 0.5 (sigmoid-via-tanh); bhh folded for r,z.
__device__ __align__(128) float g_GI2[2 * VOC * G3];
// Pre-packed bf16 B fragments (m16n8k16): [dir][nb][kc][lane] = uint2(b0,b1)
// nb<8 rows pre-scaled 0.5.
__device__ uint2 g_WF[2 * 12 * 2 * 32];

__device__ __forceinline__ unsigned packbf(float lo, float hi) {
    unsigned d;
    asm("cvt.rn.bf16x2.f32 %0, %1, %2;" : "=r"(d) : "f"(hi), "f"(lo));
    return d;
}
__device__ __forceinline__ float tanhapx(float x) {
    float r;
    asm("tanh.approx.f32 %0, %1;" : "=f"(r) : "f"(x));
    return r;
}
__device__ __forceinline__ void mma_bf16(float* d, const unsigned* a,
                                         unsigned b0, unsigned b1) {
    asm("mma.sync.aligned.m16n8k16.row.col.f32.bf16.bf16.f32 "
        "{%0,%1,%2,%3}, {%4,%5,%6,%7}, {%8,%9}, {%0,%1,%2,%3};"
        : "+f"(d[0]), "+f"(d[1]), "+f"(d[2]), "+f"(d[3])
        : "r"(a[0]), "r"(a[1]), "r"(a[2]), "r"(a[3]),
          "r"(b0), "r"(b1));
}
__device__ __forceinline__ void cp16(unsigned dst, const void* src) {
    asm volatile("cp.async.ca.shared.global [%0], [%1], 16;"
                 :: "r"(dst), "l"(src) : "memory");
}
__device__ __forceinline__ void cp_commit() {
    asm volatile("cp.async.commit_group;" ::: "memory");
}
__device__ __forceinline__ void cp_wait1() {
    asm volatile("cp.async.wait_group 1;" ::: "memory");
}

// ---------------------------------------------------------------------------
// Kernel 1: GI tables + bf16 B-fragment pack. grid = VOC+1, block = 192.
// ---------------------------------------------------------------------------
__global__ void build_tables(const float* __restrict__ emb,
                             const float* __restrict__ Wih_f,
                             const float* __restrict__ bih_f,
                             const float* __restrict__ bhh_f,
                             const float* __restrict__ Wih_b,
                             const float* __restrict__ bih_b,
                             const float* __restrict__ bhh_b,
                             const float* __restrict__ Whh_f,
                             const float* __restrict__ Whh_b) {
    int c   = blockIdx.x;
    int tid = threadIdx.x;
    if (c < VOC) {
        int dir = tid / 96;
        int g   = tid % 96;
        __shared__ float e[EMB];
        if (tid < EMB) e[tid] = emb[c * EMB + tid];
        __syncthreads();
        const float* Wih = dir ? Wih_b : Wih_f;
        const float* bih = dir ? bih_b : bih_f;
        const float* bhh = dir ? bhh_b : bhh_f;
        float a0 = bih[g] + (g < 64 ? bhh[g] : 0.0f);
        float a1 = 0.0f;
        const float4* wr4 = (const float4*)(Wih + g * EMB);
        #pragma unroll
        for (int k4 = 0; k4 < EMB / 4; k4++) {
            float4 wv = wr4[k4];
            a0 = fmaf(wv.x, e[4 * k4],     a0);
            a1 = fmaf(wv.y, e[4 * k4 + 1], a1);
            a0 = fmaf(wv.z, e[4 * k4 + 2], a0);
            a1 = fmaf(wv.w, e[4 * k4 + 3], a1);
        }
        float v = a0 + a1;
        if (g < 64) v *= 0.5f;               // sigmoid-via-tanh prescale
        int gate = g >> 5, j = g & 31;
        int hg = j >> 3, tg = (j >> 1) & 3, eb = j & 1;
        int pos = gate * 32 + tg * 8 + hg * 2 + eb;
        g_GI2[dir * (VOC * G3) + c * G3 + pos] = v;
    } else {
        for (int i = tid; i < 1536; i += 192) {
            int d    = i / 768;
            int rem  = i % 768;
            int nb   = rem / 64;
            int kc   = (rem / 32) & 1;
            int lane = rem & 31;
            int gid = lane >> 2, tg = lane & 3;
            const float* W = d ? Whh_b : Whh_f;
            const float* row = W + (8 * nb + gid) * HID;
            float s = (nb < 8) ? 0.5f : 1.0f;    // r,z rows prescaled
            int k0 = 16 * kc + 2 * tg;
            g_WF[i] = make_uint2(packbf(s * row[k0],     s * row[k0 + 1]),
                                 packbf(s * row[k0 + 8], s * row[k0 + 9]));
        }
    }
}

// Issue 12 cp.async (16B each) moving one step's gi into a smem buffer.
// Offsets match the register load order of the round-9 kernel.
__device__ __forceinline__ void prefetch_gi(unsigned dst,
                                            const float* __restrict__ GI,
                                            int cA, int cB, int tig) {
    const char* pA = (const char*)(GI + cA * G3) + tig * 32;
    const char* pB = (const char*)(GI + cB * G3) + tig * 32;
    cp16(dst + 0 * 512,  pA);          // ra0
    cp16(dst + 1 * 512,  pA + 16);     // ra1
    cp16(dst + 2 * 512,  pA + 128);    // za0
    cp16(dst + 3 * 512,  pA + 144);    // za1
    cp16(dst + 4 * 512,  pA + 256);    // na0
    cp16(dst + 5 * 512,  pA + 272);    // na1
    cp16(dst + 6 * 512,  pB);          // rb0
    cp16(dst + 7 * 512,  pB + 16);     // rb1
    cp16(dst + 8 * 512,  pB + 128);    // zb0
    cp16(dst + 9 * 512,  pB + 144);    // zb1
    cp16(dst + 10 * 512, pB + 256);    // nb0
    cp16(dst + 11 * 512, pB + 272);    // nb1
}

// ---------------------------------------------------------------------------
// Kernel 2: bf16 tensor-core GRU; cp.async double-buffered gi pipeline.
// 1024 blocks x 64 thr (2 warps), 7 blocks/SM -> single wave, 2048 resident
// warps (~3.5/SMSP, MUFU-pipe saturating). One warp = one 16-seq task.
// B fragments in smem; gi staged in smem via cp.async (zero-register
// prefetch); compute block identical to the round-9 structure.
// ---------------------------------------------------------------------------
__global__ __launch_bounds__(64, 7)
void gru_mma(const int* __restrict__ x,
             const float* __restrict__ bhh_f,
             const float* __restrict__ bhh_b,
             float* __restrict__ out) {
    __shared__ uint2  s_bf[12 * 2 * 32];        // 6 KB B fragments
    __shared__ float4 s_gi[2][2][12][32];       // 24 KB gi staging [warp][buf][i][lane]

    int tid  = threadIdx.x;
    int wb   = tid >> 5;
    int lane = tid & 31;
    int gid  = lane >> 2;
    int tig  = lane & 3;
    int dir  = blockIdx.x >> 9;                 // block-uniform
    int wi   = (blockIdx.x & 511) * 2 + wb;     // 0..1023
    int seq0 = wi << 4;

    {
        const uint2* src = g_WF + dir * 768;
        #pragma unroll
        for (int i = 0; i < 12; i++)
            s_bf[tid + 64 * i] = src[tid + 64 * i];
    }
    __syncthreads();

    const float* __restrict__ GI  = g_GI2 + dir * (VOC * G3);
    const float* __restrict__ bhh = dir ? bhh_b : bhh_f;

    float bnlo[4], bnhi[4];
    #pragma unroll
    for (int hg = 0; hg < 4; hg++) {
        bnlo[hg] = bhh[64 + 8 * hg + 2 * tig];
        bnhi[hg] = bhh[64 + 8 * hg + 2 * tig + 1];
    }

    const int* xA = x + (seq0 + gid) * TCH;
    const int* xB = x + (seq0 + gid + 8) * TCH;

    float hn[4][4], hmax[4][4];
    #pragma unroll
    for (int hg = 0; hg < 4; hg++)
        #pragma unroll
        for (int s = 0; s < 4; s++) { hn[hg][s] = 0.0f; hmax[hg][s] = -CUDART_INF_F; }

    // smem addr of this warp's gi buffer 0, at this lane's slot
    unsigned gi_dst = (unsigned)__cvta_generic_to_shared(&s_gi[wb][0][0][lane]);
    const int BUF_STRIDE = 12 * 32 * 16;        // 6144 B

    #define TIDX(k) (dir ? ((TCH - 1 - (k)) & (TCH - 1)) : ((k) & (TCH - 1)))

    // prologue: stage step 0 into buf0
    {
        int cA0 = xA[TIDX(0)], cB0 = xB[TIDX(0)];
        prefetch_gi(gi_dst, GI, cA0, cB0, tig);
        cp_commit();
    }
    int cA1 = xA[TIDX(1)], cB1 = xB[TIDX(1)];

    #pragma unroll 1
    for (int tt = 0; tt < TCH; ++tt) {
        // stage step tt+1 into the other buffer
        prefetch_gi(gi_dst + ((tt + 1) & 1) * BUF_STRIDE, GI, cA1, cB1, tig);
        cp_commit();
        int tn2 = TIDX(tt + 2);
        cA1 = xA[tn2]; cB1 = xB[tn2];

        // wait for step tt's buffer (1 group may remain in flight)
        cp_wait1();
        const float4* gb = &s_gi[wb][tt & 1][0][lane];
        float4 ra0 = gb[0 * 32],  ra1 = gb[1 * 32];
        float4 za0 = gb[2 * 32],  za1 = gb[3 * 32];
        float4 na0 = gb[4 * 32],  na1 = gb[5 * 32];
        float4 rb0 = gb[6 * 32],  rb1 = gb[7 * 32];
        float4 zb0 = gb[8 * 32],  zb1 = gb[9 * 32];
        float4 nb0 = gb[10 * 32], nb1 = gb[11 * 32];

        // pack A fragments (lane-local bf16)
        unsigned a[2][4];
        #pragma unroll
        for (int kc = 0; kc < 2; kc++) {
            a[kc][0] = packbf(hn[2 * kc][0],     hn[2 * kc][1]);
            a[kc][1] = packbf(hn[2 * kc][2],     hn[2 * kc][3]);
            a[kc][2] = packbf(hn[2 * kc + 1][0], hn[2 * kc + 1][1]);
            a[kc][3] = packbf(hn[2 * kc + 1][2], hn[2 * kc + 1][3]);
        }

        // accumulators: acc[nb][slot]; nb = gate*4 + hg
        float acc[12][4];
        acc[0][0]=ra0.x;  acc[0][1]=ra0.y;  acc[1][0]=ra0.z;  acc[1][1]=ra0.w;
        acc[2][0]=ra1.x;  acc[2][1]=ra1.y;  acc[3][0]=ra1.z;  acc[3][1]=ra1.w;
        acc[0][2]=rb0.x;  acc[0][3]=rb0.y;  acc[1][2]=rb0.z;  acc[1][3]=rb0.w;
        acc[2][2]=rb1.x;  acc[2][3]=rb1.y;  acc[3][2]=rb1.z;  acc[3][3]=rb1.w;
        acc[4][0]=za0.x;  acc[4][1]=za0.y;  acc[5][0]=za0.z;  acc[5][1]=za0.w;
        acc[6][0]=za1.x;  acc[6][1]=za1.y;  acc[7][0]=za1.z;  acc[7][1]=za1.w;
        acc[4][2]=zb0.x;  acc[4][3]=zb0.y;  acc[5][2]=zb0.z;  acc[5][3]=zb0.w;
        acc[6][2]=zb1.x;  acc[6][3]=zb1.y;  acc[7][2]=zb1.z;  acc[7][3]=zb1.w;
        acc[8][0]=bnlo[0];  acc[8][1]=bnhi[0];  acc[9][0]=bnlo[1];  acc[9][1]=bnhi[1];
        acc[10][0]=bnlo[2]; acc[10][1]=bnhi[2]; acc[11][0]=bnlo[3]; acc[11][1]=bnhi[3];
        acc[8][2]=bnlo[0];  acc[8][3]=bnhi[0];  acc[9][2]=bnlo[1];  acc[9][3]=bnhi[1];
        acc[10][2]=bnlo[2]; acc[10][3]=bnhi[2]; acc[11][2]=bnlo[3]; acc[11][3]=bnhi[3];

        float gin[4][4];
        gin[0][0]=na0.x; gin[0][1]=na0.y; gin[1][0]=na0.z; gin[1][1]=na0.w;
        gin[2][0]=na1.x; gin[2][1]=na1.y; gin[3][0]=na1.z; gin[3][1]=na1.w;
        gin[0][2]=nb0.x; gin[0][3]=nb0.y; gin[1][2]=nb0.z; gin[1][3]=nb0.w;
        gin[2][2]=nb1.x; gin[2][3]=nb1.y; gin[3][2]=nb1.z; gin[3][3]=nb1.w;

        #pragma unroll
        for (int kc = 0; kc < 2; kc++)
            #pragma unroll
            for (int nb = 0; nb < 12; nb++) {
                uint2 b = s_bf[(nb * 2 + kc) * 32 + lane];
                mma_bf16(acc[nb], a[kc], b.x, b.y);
            }

        // activations: r,z via sigmoid(x)=0.5+0.5*tanh(x/2) (prescaled)
        #pragma unroll
        for (int hg = 0; hg < 4; hg++)
            #pragma unroll
            for (int s = 0; s < 4; s++) {
                float r = fmaf(tanhapx(acc[hg][s]),     0.5f, 0.5f);
                float z = fmaf(tanhapx(acc[4 + hg][s]), 0.5f, 0.5f);
                float n = tanhapx(fmaf(r, acc[8 + hg][s], gin[hg][s]));
                float h = fmaf(z, hn[hg][s] - n, n);
                hn[hg][s] = h;
                hmax[hg][s] = fmaxf(hmax[hg][s], h);
            }
    }
    #undef TIDX

    int sA = seq0 + gid, sB = seq0 + gid + 8;
    #pragma unroll
    for (int hg = 0; hg < 4; hg++) {
        int col = 8 * hg + 2 * tig;
        *(float2*)(out + sA * 64 + dir * 32 + col) = make_float2(hmax[hg][0], hmax[hg][1]);
        *(float2*)(out + sB * 64 + dir * 32 + col) = make_float2(hmax[hg][2], hmax[hg][3]);
    }
}

// ---------------------------------------------------------------------------
// kernel_launch
// ---------------------------------------------------------------------------
extern "C" void kernel_launch(void* const* d_in, const int* in_sizes, int n_in,
                              void* d_out, int out_size) {
    const int*   x     = (const int*)  d_in[0];
    const float* emb   = (const float*)d_in[1];
    const float* Wih_f = (const float*)d_in[2];
    const float* Whh_f = (const float*)d_in[3];
    const float* bih_f = (const float*)d_in[4];
    const float* bhh_f = (const float*)d_in[5];
    const float* Wih_b = (const float*)d_in[6];
    const float* Whh_b = (const float*)d_in[7];
    const float* bih_b = (const float*)d_in[8];
    const float* bhh_b = (const float*)d_in[9];
    float* out = (float*)d_out;

    // prefer max shared-memory carveout so 7 blocks/SM (210 KB) fit
    cudaFuncSetAttribute(gru_mma,
                         cudaFuncAttributePreferredSharedMemoryCarveout, 100);

    build_tables<<<VOC + 1, 192>>>(emb, Wih_f, bih_f, bhh_f,
                                   Wih_b, bih_b, bhh_b, Whh_f, Whh_b);

    // 1024 blocks x 2 warps = 2048 warps, one 16-seq task each.
    // 7 blocks/SM -> single wave. Blocks 0..511 dir0, 512..1023 dir1.
    gru_mma<<<1024, 64>>>(x, bhh_f, bhh_b, out);
}

// round 14
// speedup vs baseline: 1.3198x; 1.3198x over previous
#include <cuda_runtime.h>
#include <cuda_fp16.h>
#include <math_constants.h>

#define BATCH 64
#define SEQ   256
#define TCH   16
#define VOC   262
#define EMB   64
#define HID   32
#define G3    96
#define NSEQ  (BATCH*SEQ)

// Tables (device globals — no allocation allowed)
// GI row (384B stride): floats [0..63] = r,z pre-acts (permuted
// pos = gate*32 + tig*8 + hg*2 + e, prescaled 0.5, bhh folded);
// bytes [256..320) = n pre-acts as 32 f16 (same permute, NOT prescaled,
// bih folded only). Rest pad.
__device__ __align__(128) float g_GI2[2 * VOC * G3];
// Pre-packed f16 B fragments (m16n8k16): [dir][nb][kc][lane] = uint2(b0,b1)
// nb<8 rows pre-scaled 0.5.
__device__ uint2 g_WF[2 * 12 * 2 * 32];

#define H05   0x38003800u    // f16x2 (0.5, 0.5)
#define HNINF 0xFC00FC00u    // f16x2 (-inf, -inf)

__device__ __forceinline__ unsigned pack2h(float lo, float hi) {
    unsigned d;
    asm("cvt.rn.f16x2.f32 %0, %1, %2;" : "=r"(d) : "f"(hi), "f"(lo));
    return d;
}
__device__ __forceinline__ unsigned tanh2(unsigned x) {
    unsigned d;
    asm("tanh.approx.f16x2 %0, %1;" : "=r"(d) : "r"(x));
    return d;
}
__device__ __forceinline__ unsigned fma2(unsigned a, unsigned b, unsigned c) {
    unsigned d;
    asm("fma.rn.f16x2 %0, %1, %2, %3;" : "=r"(d) : "r"(a), "r"(b), "r"(c));
    return d;
}
__device__ __forceinline__ unsigned sub2(unsigned a, unsigned b) {
    unsigned d;
    asm("sub.rn.f16x2 %0, %1, %2;" : "=r"(d) : "r"(a), "r"(b));
    return d;
}
__device__ __forceinline__ unsigned max2(unsigned a, unsigned b) {
    unsigned d;
    asm("max.f16x2 %0, %1, %2;" : "=r"(d) : "r"(a), "r"(b));
    return d;
}
__device__ __forceinline__ void mma_f16(float* d, const unsigned* a,
                                        unsigned b0, unsigned b1) {
    asm("mma.sync.aligned.m16n8k16.row.col.f32.f16.f16.f32 "
        "{%0,%1,%2,%3}, {%4,%5,%6,%7}, {%8,%9}, {%0,%1,%2,%3};"
        : "+f"(d[0]), "+f"(d[1]), "+f"(d[2]), "+f"(d[3])
        : "r"(a[0]), "r"(a[1]), "r"(a[2]), "r"(a[3]),
          "r"(b0), "r"(b1));
}

// ---------------------------------------------------------------------------
// Kernel 1: GI tables (r,z f32 prescaled; n f16) + f16 B-fragment pack.
// grid = VOC+1, block = 192.
// ---------------------------------------------------------------------------
__global__ void build_tables(const float* __restrict__ emb,
                             const float* __restrict__ Wih_f,
                             const float* __restrict__ bih_f,
                             const float* __restrict__ bhh_f,
                             const float* __restrict__ Wih_b,
                             const float* __restrict__ bih_b,
                             const float* __restrict__ bhh_b,
                             const float* __restrict__ Whh_f,
                             const float* __restrict__ Whh_b) {
    int c   = blockIdx.x;
    int tid = threadIdx.x;
    if (c < VOC) {
        int dir = tid / 96;
        int g   = tid % 96;
        __shared__ float e[EMB];
        if (tid < EMB) e[tid] = emb[c * EMB + tid];
        __syncthreads();
        const float* Wih = dir ? Wih_b : Wih_f;
        const float* bih = dir ? bih_b : bih_f;
        const float* bhh = dir ? bhh_b : bhh_f;
        float a0 = bih[g] + (g < 64 ? bhh[g] : 0.0f);
        float a1 = 0.0f;
        const float4* wr4 = (const float4*)(Wih + g * EMB);
        #pragma unroll
        for (int k4 = 0; k4 < EMB / 4; k4++) {
            float4 wv = wr4[k4];
            a0 = fmaf(wv.x, e[4 * k4],     a0);
            a1 = fmaf(wv.y, e[4 * k4 + 1], a1);
            a0 = fmaf(wv.z, e[4 * k4 + 2], a0);
            a1 = fmaf(wv.w, e[4 * k4 + 3], a1);
        }
        float v = a0 + a1;
        int j  = g & 31;
        int hg = j >> 3, tg = (j >> 1) & 3, eb = j & 1;
        int p  = tg * 8 + hg * 2 + eb;
        char* rowbase = (char*)g_GI2 + (dir * VOC + c) * (G3 * 4);
        if (g < 64) {
            // r,z: f32, prescaled for sigmoid-via-tanh
            int gate = g >> 5;
            ((float*)rowbase)[gate * 32 + p] = v * 0.5f;
        } else {
            // n: f16, not prescaled
            *(__half*)(rowbase + 256 + p * 2) = __float2half_rn(v);
        }
    } else {
        // pack f16 B fragments (2*12*2*32 = 1536 uint2)
        for (int i = tid; i < 1536; i += 192) {
            int d    = i / 768;
            int rem  = i % 768;
            int nb   = rem / 64;
            int kc   = (rem / 32) & 1;
            int lane = rem & 31;
            int gid = lane >> 2, tg = lane & 3;
            const float* W = d ? Whh_b : Whh_f;
            const float* row = W + (8 * nb + gid) * HID;
            float s = (nb < 8) ? 0.5f : 1.0f;    // r,z rows prescaled
            int k0 = 16 * kc + 2 * tg;
            g_WF[i] = make_uint2(pack2h(s * row[k0],     s * row[k0 + 1]),
                                 pack2h(s * row[k0 + 8], s * row[k0 + 9]));
        }
    }
}

// ---------------------------------------------------------------------------
// Kernel 2: f16 tensor-core GRU (R9 skeleton). One warp = 16 seqs x 2 tasks.
// h lives as f16x2 pairs == the MMA A fragments (zero per-step repacking).
// 24 f16 MMAs/step, 24 MUFU.TANH (f16x2) /step, register gi double-buffer.
// Blocks dir-uniform: dir = blockIdx.x >> 8.
// ---------------------------------------------------------------------------
__global__ __launch_bounds__(64, 4)
void gru_mma(const int* __restrict__ x,
             const float* __restrict__ bhh_f,
             const float* __restrict__ bhh_b,
             float* __restrict__ out) {
    int tid  = threadIdx.x;
    int wb   = tid >> 5;
    int lane = tid & 31;
    int gid  = lane >> 2;
    int tig  = lane & 3;
    int dir  = blockIdx.x >> 8;                 // block-uniform
    int wi   = (blockIdx.x & 255) * 2 + wb;     // 0..511

    const float* __restrict__ GI  = g_GI2 + dir * (VOC * G3);
    const float* __restrict__ bhh = dir ? bhh_b : bhh_f;

    // B fragments in registers (f16x2)
    unsigned bf[12][2][2];
    {
        const uint2* WF = g_WF + dir * 768;
        #pragma unroll
        for (int nb = 0; nb < 12; nb++)
            #pragma unroll
            for (int kc = 0; kc < 2; kc++) {
                uint2 v = WF[(nb * 2 + kc) * 32 + lane];
                bf[nb][kc][0] = v.x;
                bf[nb][kc][1] = v.y;
            }
    }
    float bnlo[4], bnhi[4];
    #pragma unroll
    for (int hg = 0; hg < 4; hg++) {
        bnlo[hg] = bhh[64 + 8 * hg + 2 * tig];
        bnhi[hg] = bhh[64 + 8 * hg + 2 * tig + 1];
    }

    #pragma unroll 1
    for (int task = 0; task < 2; task++) {
        int seq0 = (wi + task * 512) << 4;
        const int* xA = x + (seq0 + gid) * TCH;
        const int* xB = x + (seq0 + gid + 8) * TCH;

        // h and running max as f16x2 pairs: [hg][0]=rowA (e0,e1), [1]=rowB
        unsigned hp[4][2], hm[4][2];
        #pragma unroll
        for (int hg = 0; hg < 4; hg++) {
            hp[hg][0] = 0u;    hp[hg][1] = 0u;
            hm[hg][0] = HNINF; hm[hg][1] = HNINF;
        }

        #define TIDX(k) (dir ? ((TCH - 1 - (k)) & (TCH - 1)) : ((k) & (TCH - 1)))

        int cA = xA[TIDX(0)], cB = xB[TIDX(0)];

        // gi for step 0 (current buffer: 8 float4 r/z + 2 uint4 n)
        const char* bA = (const char*)(GI + cA * G3);
        const char* bB = (const char*)(GI + cB * G3);
        float4 ra0 = ((const float4*)bA)[tig * 2];
        float4 ra1 = ((const float4*)bA)[tig * 2 + 1];
        float4 za0 = ((const float4*)bA)[8 + tig * 2];
        float4 za1 = ((const float4*)bA)[8 + tig * 2 + 1];
        uint4  nA  = *(const uint4*)(bA + 256 + tig * 16);
        float4 rb0 = ((const float4*)bB)[tig * 2];
        float4 rb1 = ((const float4*)bB)[tig * 2 + 1];
        float4 zb0 = ((const float4*)bB)[8 + tig * 2];
        float4 zb1 = ((const float4*)bB)[8 + tig * 2 + 1];
        uint4  nB  = *(const uint4*)(bB + 256 + tig * 16);

        int cA1 = xA[TIDX(1)], cB1 = xB[TIDX(1)];

        #pragma unroll 1
        for (int tt = 0; tt < TCH; ++tt) {
            // --- prefetch gi for step tt+1 ---
            const char* pA = (const char*)(GI + cA1 * G3);
            const char* pB = (const char*)(GI + cB1 * G3);
            float4 pra0 = ((const float4*)pA)[tig * 2];
            float4 pra1 = ((const float4*)pA)[tig * 2 + 1];
            float4 pza0 = ((const float4*)pA)[8 + tig * 2];
            float4 pza1 = ((const float4*)pA)[8 + tig * 2 + 1];
            uint4  pnA  = *(const uint4*)(pA + 256 + tig * 16);
            float4 prb0 = ((const float4*)pB)[tig * 2];
            float4 prb1 = ((const float4*)pB)[tig * 2 + 1];
            float4 pzb0 = ((const float4*)pB)[8 + tig * 2];
            float4 pzb1 = ((const float4*)pB)[8 + tig * 2 + 1];
            uint4  pnB  = *(const uint4*)(pB + 256 + tig * 16);

            int tn2 = TIDX(tt + 2);
            cA1 = xA[tn2]; cB1 = xB[tn2];

            // --- A fragments ARE the h registers ---
            unsigned a0[4] = {hp[0][0], hp[0][1], hp[1][0], hp[1][1]};
            unsigned a1[4] = {hp[2][0], hp[2][1], hp[3][0], hp[3][1]};

            // accumulators: acc[nb][slot]; nb = gate*4 + hg
            float acc[12][4];
            acc[0][0]=ra0.x;  acc[0][1]=ra0.y;  acc[1][0]=ra0.z;  acc[1][1]=ra0.w;
            acc[2][0]=ra1.x;  acc[2][1]=ra1.y;  acc[3][0]=ra1.z;  acc[3][1]=ra1.w;
            acc[0][2]=rb0.x;  acc[0][3]=rb0.y;  acc[1][2]=rb0.z;  acc[1][3]=rb0.w;
            acc[2][2]=rb1.x;  acc[2][3]=rb1.y;  acc[3][2]=rb1.z;  acc[3][3]=rb1.w;
            acc[4][0]=za0.x;  acc[4][1]=za0.y;  acc[5][0]=za0.z;  acc[5][1]=za0.w;
            acc[6][0]=za1.x;  acc[6][1]=za1.y;  acc[7][0]=za1.z;  acc[7][1]=za1.w;
            acc[4][2]=zb0.x;  acc[4][3]=zb0.y;  acc[5][2]=zb0.z;  acc[5][3]=zb0.w;
            acc[6][2]=zb1.x;  acc[6][3]=zb1.y;  acc[7][2]=zb1.z;  acc[7][3]=zb1.w;
            acc[8][0]=bnlo[0];  acc[8][1]=bnhi[0];  acc[9][0]=bnlo[1];  acc[9][1]=bnhi[1];
            acc[10][0]=bnlo[2]; acc[10][1]=bnhi[2]; acc[11][0]=bnlo[3]; acc[11][1]=bnhi[3];
            acc[8][2]=bnlo[0];  acc[8][3]=bnhi[0];  acc[9][2]=bnlo[1];  acc[9][3]=bnhi[1];
            acc[10][2]=bnlo[2]; acc[10][3]=bnhi[2]; acc[11][2]=bnlo[3]; acc[11][3]=bnhi[3];

            #pragma unroll
            for (int nb = 0; nb < 12; nb++) {
                mma_f16(acc[nb], a0, bf[nb][0][0], bf[nb][0][1]);
                mma_f16(acc[nb], a1, bf[nb][1][0], bf[nb][1][1]);
            }

            // f16x2 activations (2 hidden units per op)
            unsigned ginA[4] = {nA.x, nA.y, nA.z, nA.w};
            unsigned ginB[4] = {nB.x, nB.y, nB.z, nB.w};
            #pragma unroll
            for (int hg = 0; hg < 4; hg++) {
                // rowA (slots 0,1)
                {
                    unsigned r2 = fma2(tanh2(pack2h(acc[hg][0], acc[hg][1])), H05, H05);
                    unsigned z2 = fma2(tanh2(pack2h(acc[4+hg][0], acc[4+hg][1])), H05, H05);
                    unsigned gh = pack2h(acc[8+hg][0], acc[8+hg][1]);
                    unsigned n2 = tanh2(fma2(r2, gh, ginA[hg]));
                    unsigned h2 = fma2(z2, sub2(hp[hg][0], n2), n2);
                    hp[hg][0] = h2;
                    hm[hg][0] = max2(hm[hg][0], h2);
                }
                // rowB (slots 2,3)
                {
                    unsigned r2 = fma2(tanh2(pack2h(acc[hg][2], acc[hg][3])), H05, H05);
                    unsigned z2 = fma2(tanh2(pack2h(acc[4+hg][2], acc[4+hg][3])), H05, H05);
                    unsigned gh = pack2h(acc[8+hg][2], acc[8+hg][3]);
                    unsigned n2 = tanh2(fma2(r2, gh, ginB[hg]));
                    unsigned h2 = fma2(z2, sub2(hp[hg][1], n2), n2);
                    hp[hg][1] = h2;
                    hm[hg][1] = max2(hm[hg][1], h2);
                }
            }

            // rotate prefetch buffer into current
            ra0 = pra0; ra1 = pra1; za0 = pza0; za1 = pza1; nA = pnA;
            rb0 = prb0; rb1 = prb1; zb0 = pzb0; zb1 = pzb1; nB = pnB;
        }
        #undef TIDX

        int sA = seq0 + gid, sB = seq0 + gid + 8;
        #pragma unroll
        for (int hg = 0; hg < 4; hg++) {
            int col = 8 * hg + 2 * tig;
            float2 fa = __half22float2(*(__half2*)&hm[hg][0]);
            float2 fb = __half22float2(*(__half2*)&hm[hg][1]);
            *(float2*)(out + sA * 64 + dir * 32 + col) = fa;
            *(float2*)(out + sB * 64 + dir * 32 + col) = fb;
        }
    }
}

// ---------------------------------------------------------------------------
// kernel_launch
// ---------------------------------------------------------------------------
extern "C" void kernel_launch(void* const* d_in, const int* in_sizes, int n_in,
                              void* d_out, int out_size) {
    const int*   x     = (const int*)  d_in[0];
    const float* emb   = (const float*)d_in[1];
    const float* Wih_f = (const float*)d_in[2];
    const float* Whh_f = (const float*)d_in[3];
    const float* bih_f = (const float*)d_in[4];
    const float* bhh_f = (const float*)d_in[5];
    const float* Wih_b = (const float*)d_in[6];
    const float* Whh_b = (const float*)d_in[7];
    const float* bih_b = (const float*)d_in[8];
    const float* bhh_b = (const float*)d_in[9];
    float* out = (float*)d_out;

    build_tables<<<VOC + 1, 192>>>(emb, Wih_f, bih_f, bhh_f,
                                   Wih_b, bih_b, bhh_b, Whh_f, Whh_b);

    // R9 skeleton: 512 blocks x 2 warps = 1024 warps, 2 tasks each.
    // Blocks 0..255 dir0, 256..511 dir1.
    gru_mma<<<512, 64>>>(x, bhh_f, bhh_b, out);
}